// round 2
// baseline (speedup 1.0000x reference)
#include <cuda_runtime.h>
#include <cstdint>

// Problem constants
#define BB 8
#define CC 256
#define NN 4096
#define DD 32

// ---------------------------------------------------------------------------
// Scratch (device globals — no allocation allowed)
// ---------------------------------------------------------------------------
__device__ float g_Q[BB * DD * NN];                 // [b][d][n]   4 MB
__device__ float g_K[BB * DD * NN];                 // [b][d][m]   4 MB
__device__ float g_Vt[(size_t)BB * NN * CC];        // [b][m][c]  32 MB (transposed V)
__device__ float g_RZ[BB * NN];                     // 1 / Z[m]

// ---------------------------------------------------------------------------
// Kernel 1: 1x1-conv projection  out[r][n] = sum_c W[r][c] x[c][n] + bias[r]
// CTA tile: 32 rows x 128 cols, 256 threads, 4x4 microtile.
// transposeOut=1 writes out as [b][n][r] (used for V -> g_Vt).
// ---------------------------------------------------------------------------
__global__ __launch_bounds__(256) void proj_kernel(
    const float* __restrict__ x, const float* __restrict__ W,
    const float* __restrict__ bias, float* __restrict__ out,
    int Rtot, int transposeOut)
{
    __shared__ float W_s[32][32];
    __shared__ float x_s[32][128];

    const int tid = threadIdx.x;
    const int b  = blockIdx.z;
    const int r0 = blockIdx.y * 32;
    const int n0 = blockIdx.x * 128;
    const int tr = tid >> 5;   // 0..7  -> 4 rows each
    const int tc = tid & 31;   // 0..31 -> 4 cols each

    const float* xb = x + (size_t)b * CC * NN;

    float acc[4][4];
#pragma unroll
    for (int i = 0; i < 4; i++)
#pragma unroll
        for (int j = 0; j < 4; j++) acc[i][j] = 0.0f;

    for (int kk = 0; kk < CC; kk += 32) {
        // W tile 32x32
        for (int i = tid; i < 32 * 32; i += 256) {
            int rr = i >> 5, cc = i & 31;
            W_s[rr][cc] = W[(r0 + rr) * CC + kk + cc];
        }
        // x tile 32x128 (float4 coalesced)
        for (int i = tid; i < 32 * 32; i += 256) {
            int cc = i >> 5;
            int j4 = (i & 31) << 2;
            float4 v = *reinterpret_cast<const float4*>(xb + (size_t)(kk + cc) * NN + n0 + j4);
            *reinterpret_cast<float4*>(&x_s[cc][j4]) = v;
        }
        __syncthreads();

#pragma unroll 8
        for (int kc = 0; kc < 32; kc++) {
            float4 xv = *reinterpret_cast<const float4*>(&x_s[kc][tc * 4]);
            float wv[4];
#pragma unroll
            for (int i = 0; i < 4; i++) wv[i] = W_s[tr * 4 + i][kc];
#pragma unroll
            for (int i = 0; i < 4; i++) {
                acc[i][0] += wv[i] * xv.x;
                acc[i][1] += wv[i] * xv.y;
                acc[i][2] += wv[i] * xv.z;
                acc[i][3] += wv[i] * xv.w;
            }
        }
        __syncthreads();
    }

    if (!transposeOut) {
#pragma unroll
        for (int i = 0; i < 4; i++) {
            int r = r0 + tr * 4 + i;
            float bbv = bias[r];
            float4 v = make_float4(acc[i][0] + bbv, acc[i][1] + bbv,
                                   acc[i][2] + bbv, acc[i][3] + bbv);
            *reinterpret_cast<float4*>(out + ((size_t)b * Rtot + r) * NN + n0 + tc * 4) = v;
        }
    } else {
        // out[b][n][r]  (Rtot == CC for V)
        float bb0 = bias[r0 + tr * 4 + 0];
        float bb1 = bias[r0 + tr * 4 + 1];
        float bb2 = bias[r0 + tr * 4 + 2];
        float bb3 = bias[r0 + tr * 4 + 3];
#pragma unroll
        for (int j = 0; j < 4; j++) {
            int n = n0 + tc * 4 + j;
            float4 v = make_float4(acc[0][j] + bb0, acc[1][j] + bb1,
                                   acc[2][j] + bb2, acc[3][j] + bb3);
            *reinterpret_cast<float4*>(out + ((size_t)b * NN + n) * CC + r0 + tr * 4) = v;
        }
    }
}

// ---------------------------------------------------------------------------
// Kernel 2: pass A — column sums  Z[m] = sum_n exp(q_n . k_m), store 1/Z.
// CTA: one 128-wide m-tile per batch, streams all n in 128-tiles.
// 256 threads as 16x16 grid, 8x8 microtile of S.
// ---------------------------------------------------------------------------
__global__ __launch_bounds__(256) void colsum_kernel()
{
    __shared__ float K_s[DD][128];
    __shared__ float Q_s[DD][128];
    __shared__ float zs[16][128];

    const int tid = threadIdx.x;
    const int b  = blockIdx.y;
    const int m0 = blockIdx.x * 128;

    const float* Qb = g_Q + (size_t)b * DD * NN;
    const float* Kb = g_K + (size_t)b * DD * NN;

    // K tile (resident for whole kernel)
    for (int i = tid; i < DD * 32; i += 256) {
        int d = i >> 5;
        int j4 = (i & 31) << 2;
        *reinterpret_cast<float4*>(&K_s[d][j4]) =
            *reinterpret_cast<const float4*>(Kb + (size_t)d * NN + m0 + j4);
    }

    const int tn = tid >> 4;   // 0..15 (n groups of 8)
    const int tm = tid & 15;   // 0..15 (m groups of 8)

    float zacc[8];
#pragma unroll
    for (int j = 0; j < 8; j++) zacc[j] = 0.0f;

    for (int n0 = 0; n0 < NN; n0 += 128) {
        __syncthreads();  // previous compute done (also fences K_s load on iter 0)
        for (int i = tid; i < DD * 32; i += 256) {
            int d = i >> 5;
            int j4 = (i & 31) << 2;
            *reinterpret_cast<float4*>(&Q_s[d][j4]) =
                *reinterpret_cast<const float4*>(Qb + (size_t)d * NN + n0 + j4);
        }
        __syncthreads();

        float s[8][8];
#pragma unroll
        for (int i = 0; i < 8; i++)
#pragma unroll
            for (int j = 0; j < 8; j++) s[i][j] = 0.0f;

#pragma unroll 4
        for (int d = 0; d < DD; d++) {
            float4 q0 = *reinterpret_cast<const float4*>(&Q_s[d][tn * 8]);
            float4 q1 = *reinterpret_cast<const float4*>(&Q_s[d][tn * 8 + 4]);
            float4 k0 = *reinterpret_cast<const float4*>(&K_s[d][tm * 8]);
            float4 k1 = *reinterpret_cast<const float4*>(&K_s[d][tm * 8 + 4]);
            float qv[8] = {q0.x, q0.y, q0.z, q0.w, q1.x, q1.y, q1.z, q1.w};
            float kv[8] = {k0.x, k0.y, k0.z, k0.w, k1.x, k1.y, k1.z, k1.w};
#pragma unroll
            for (int i = 0; i < 8; i++)
#pragma unroll
                for (int j = 0; j < 8; j++) s[i][j] += qv[i] * kv[j];
        }
#pragma unroll
        for (int i = 0; i < 8; i++)
#pragma unroll
            for (int j = 0; j < 8; j++) zacc[j] += __expf(s[i][j]);
    }

    // reduce the 16 n-groups per m column
#pragma unroll
    for (int j = 0; j < 8; j++) zs[tn][tm * 8 + j] = zacc[j];
    __syncthreads();
    if (tid < 128) {
        float z = 0.0f;
#pragma unroll
        for (int i = 0; i < 16; i++) z += zs[i][tid];
        g_RZ[(size_t)b * NN + m0 + tid] = 1.0f / z;
    }
}

// ---------------------------------------------------------------------------
// Kernel 3: scale Vt[b][m][c] *= 1/Z[m]
// ---------------------------------------------------------------------------
__global__ __launch_bounds__(256) void scale_vt_kernel()
{
    size_t idx = (size_t)blockIdx.x * 256 + threadIdx.x;   // float4 index
    float4* p = reinterpret_cast<float4*>(g_Vt);
    float4 v = p[idx];
    size_t g = idx >> 6;           // CC/4 = 64 float4 per m
    size_t m = g & (NN - 1);
    size_t b = g >> 12;
    float rz = g_RZ[b * NN + m];
    v.x *= rz; v.y *= rz; v.z *= rz; v.w *= rz;
    p[idx] = v;
}

// ---------------------------------------------------------------------------
// Kernel 4: pass B — out[b][c][n] = sum_m exp(q_n . k_m) * Vt[b][m][c]
// CTA: 64-query n-tile, loops m in 64-tiles.
//   S: 16x16 thread grid, 4x4 microtile -> P_s (exp'd)
//   PV: 8x32 thread grid, 8n x 8c microtile; V staged [m][c] in smem.
// ---------------------------------------------------------------------------
__global__ __launch_bounds__(256, 2) void attn_out_kernel(float* __restrict__ out)
{
    extern __shared__ float sm[];
    float* Q_s = sm;                    // [32][64]
    float* K_s = Q_s + 32 * 64;         // [32][64]
    float* P_s = K_s + 32 * 64;         // [64][64]
    float* V_s = P_s + 64 * 64;         // [64][256]

    const int tid = threadIdx.x;
    const int b  = blockIdx.y;
    const int n0 = blockIdx.x * 64;

    const float* Qb = g_Q + (size_t)b * DD * NN;
    const float* Kb = g_K + (size_t)b * DD * NN;
    const float* Vb = g_Vt + (size_t)b * NN * CC;

    // Q tile (resident)
    for (int i = tid; i < 32 * 16; i += 256) {
        int d = i >> 4;
        int j4 = (i & 15) << 2;
        *reinterpret_cast<float4*>(&Q_s[d * 64 + j4]) =
            *reinterpret_cast<const float4*>(Qb + (size_t)d * NN + n0 + j4);
    }

    const int tn_s = tid >> 4, tm_s = tid & 15;   // S phase: 16x16
    const int tn_o = tid >> 5, tc_o = tid & 31;   // PV phase: 8x32

    float o[8][8];
#pragma unroll
    for (int i = 0; i < 8; i++)
#pragma unroll
        for (int j = 0; j < 8; j++) o[i][j] = 0.0f;

    for (int m0 = 0; m0 < NN; m0 += 64) {
        __syncthreads();   // previous PV done; safe to overwrite tiles
        for (int i = tid; i < 32 * 16; i += 256) {
            int d = i >> 4;
            int j4 = (i & 15) << 2;
            *reinterpret_cast<float4*>(&K_s[d * 64 + j4]) =
                *reinterpret_cast<const float4*>(Kb + (size_t)d * NN + m0 + j4);
        }
        for (int i = tid; i < 64 * 64; i += 256) {
            int j  = i >> 6;
            int c4 = (i & 63) << 2;
            *reinterpret_cast<float4*>(&V_s[j * 256 + c4]) =
                *reinterpret_cast<const float4*>(Vb + (size_t)(m0 + j) * CC + c4);
        }
        __syncthreads();

        // S = Q^T K  (64x64), then P = exp(S)
        float s[4][4];
#pragma unroll
        for (int i = 0; i < 4; i++)
#pragma unroll
            for (int j = 0; j < 4; j++) s[i][j] = 0.0f;

#pragma unroll 8
        for (int d = 0; d < DD; d++) {
            float4 q4 = *reinterpret_cast<const float4*>(&Q_s[d * 64 + tn_s * 4]);
            float4 k4 = *reinterpret_cast<const float4*>(&K_s[d * 64 + tm_s * 4]);
            float qv[4] = {q4.x, q4.y, q4.z, q4.w};
            float kv[4] = {k4.x, k4.y, k4.z, k4.w};
#pragma unroll
            for (int i = 0; i < 4; i++)
#pragma unroll
                for (int j = 0; j < 4; j++) s[i][j] += qv[i] * kv[j];
        }
#pragma unroll
        for (int i = 0; i < 4; i++) {
            float4 pv = make_float4(__expf(s[i][0]), __expf(s[i][1]),
                                    __expf(s[i][2]), __expf(s[i][3]));
            *reinterpret_cast<float4*>(&P_s[(tn_s * 4 + i) * 64 + tm_s * 4]) = pv;
        }
        __syncthreads();

        // O += P @ V_s   (64n x 256c)
#pragma unroll 2
        for (int m = 0; m < 64; m++) {
            float4 va = *reinterpret_cast<const float4*>(&V_s[m * 256 + tc_o * 4]);
            float4 vb4 = *reinterpret_cast<const float4*>(&V_s[m * 256 + 128 + tc_o * 4]);
            float pr[8];
#pragma unroll
            for (int i = 0; i < 8; i++) pr[i] = P_s[(tn_o * 8 + i) * 64 + m];
#pragma unroll
            for (int i = 0; i < 8; i++) {
                o[i][0] += pr[i] * va.x;  o[i][1] += pr[i] * va.y;
                o[i][2] += pr[i] * va.z;  o[i][3] += pr[i] * va.w;
                o[i][4] += pr[i] * vb4.x; o[i][5] += pr[i] * vb4.y;
                o[i][6] += pr[i] * vb4.z; o[i][7] += pr[i] * vb4.w;
            }
        }
    }

    // write out[b][c][n0 + n] — per c, the thread's 8 n's are consecutive
    float* ob = out + (size_t)b * CC * NN;
#pragma unroll
    for (int j = 0; j < 8; j++) {
        int c = (j < 4) ? (tc_o * 4 + j) : (128 + tc_o * 4 + (j - 4));
        float4 v0 = make_float4(o[0][j], o[1][j], o[2][j], o[3][j]);
        float4 v1 = make_float4(o[4][j], o[5][j], o[6][j], o[7][j]);
        float* dst = ob + (size_t)c * NN + n0 + tn_o * 8;
        *reinterpret_cast<float4*>(dst)     = v0;
        *reinterpret_cast<float4*>(dst + 4) = v1;
    }
}

// ---------------------------------------------------------------------------
// Launch
// ---------------------------------------------------------------------------
extern "C" void kernel_launch(void* const* d_in, const int* in_sizes, int n_in,
                              void* d_out, int out_size)
{
    const float* x  = (const float*)d_in[0];
    const float* Wq = (const float*)d_in[1];
    const float* bq = (const float*)d_in[2];
    const float* Wk = (const float*)d_in[3];
    const float* bk = (const float*)d_in[4];
    const float* Wv = (const float*)d_in[5];
    const float* bv = (const float*)d_in[6];
    float* out = (float*)d_out;

    float *Qp, *Kp, *Vtp;
    cudaGetSymbolAddress((void**)&Qp,  g_Q);
    cudaGetSymbolAddress((void**)&Kp,  g_K);
    cudaGetSymbolAddress((void**)&Vtp, g_Vt);

    const int smem_bytes = (32 * 64 + 32 * 64 + 64 * 64 + 64 * 256) * 4;  // 96 KB
    cudaFuncSetAttribute(attn_out_kernel,
                         cudaFuncAttributeMaxDynamicSharedMemorySize, smem_bytes);

    // projections
    proj_kernel<<<dim3(NN / 128, 1, BB), 256>>>(x, Wq, bq, Qp, DD, 0);
    proj_kernel<<<dim3(NN / 128, 1, BB), 256>>>(x, Wk, bk, Kp, DD, 0);
    proj_kernel<<<dim3(NN / 128, CC / 32, BB), 256>>>(x, Wv, bv, Vtp, CC, 1);

    // pass A: 1/Z[m]
    colsum_kernel<<<dim3(NN / 128, BB), 256>>>();

    // V <- V / Z
    scale_vt_kernel<<<(BB * NN * CC / 4) / 256, 256>>>();

    // pass B: output
    attn_out_kernel<<<dim3(NN / 64, BB), 256, smem_bytes>>>(out);
}